// round 2
// baseline (speedup 1.0000x reference)
#include <cuda_runtime.h>

#define BB   8192
#define LL   40
#define VV   100000
#define EE   64
#define ALLD 456

// ---------------- device scratch (no allocations allowed) ----------------
__device__ float g_Wq[80 * 128];     // [j][k] = W1[k][j] + W1[256+k][j]
__device__ float g_Ws[128 * 80];     // [k][j] = W1[128+k][j] - W1[256+k][j]
__device__ float g_Wp[128 * 80];     // [k][j] = W1[384+k][j]
__device__ float g_W1fT[80 * 456];   // [j][i] = ffn_W1[i][j] * bn_scale[i]
__device__ float g_b1f[80];          // BN-folded bias
__device__ float g_X[(size_t)BB * ALLD];

__device__ __forceinline__ float sigmoidf_(float x) { return 1.f / (1.f + __expf(-x)); }

// ---------------- prep: fold weights ----------------
__global__ void din_prep(const float* __restrict__ attW1,
                         const float* __restrict__ ffnW1,
                         const float* __restrict__ ffnb1,
                         const float* __restrict__ gam,
                         const float* __restrict__ bet,
                         const float* __restrict__ mu,
                         const float* __restrict__ var)
{
    int idx = blockIdx.x * 256 + threadIdx.x;
    if (idx < 10240) {
        int k = idx / 80, j = idx - k * 80;
        float wa = attW1[k * 80 + j];
        float wb = attW1[(128 + k) * 80 + j];
        float wc = attW1[(256 + k) * 80 + j];
        float wd = attW1[(384 + k) * 80 + j];
        g_Wq[j * 128 + k] = wa + wc;
        g_Ws[idx] = wb - wc;
        g_Wp[idx] = wd;
    } else if (idx < 10240 + 36480) {
        int t = idx - 10240;
        int j = t / 456, i = t - j * 456;
        float sc = gam[i] * rsqrtf(var[i] + 1e-3f);
        g_W1fT[t] = ffnW1[i * 80 + j] * sc;
    } else if (idx < 10240 + 36480 + 80) {
        int j = idx - (10240 + 36480);
        float acc = ffnb1[j];
        for (int i = 0; i < 456; i++) {
            float sc = gam[i] * rsqrtf(var[i] + 1e-3f);
            acc += (bet[i] - mu[i] * sc) * ffnW1[i * 80 + j];
        }
        g_b1f[j] = acc;
    }
}

// ---------------- main: attention per batch element ----------------
// smem layout (floats)
#define SM_S    0        // 40 x 132 (stride 132, float4-aligned)
#define SM_WEFF 5280     // 128 x 88
#define SM_A1   16544    // 40 x 81
#define SM_W2   19784    // 80 x 41
#define SM_A2   23064    // 40 x 41
#define SM_Q    24704    // 128
#define SM_QB   24832    // 80
#define SM_WF   24912    // 40
#define SM_B2   24952    // 40
#define SM_LOG  24992    // 40
#define SM_ATT  25032    // 40
#define SM_RED  25072    // 2
#define SM_MAIN_FLOATS 25076

__global__ void __launch_bounds__(256, 2) din_main(
    const float* __restrict__ dense, const int* __restrict__ sparse,
    const int* __restrict__ seq, const int* __restrict__ item,
    const float* __restrict__ emb_sp, const float* __restrict__ emb_seq,
    const float* __restrict__ att_b1, const float* __restrict__ attW2,
    const float* __restrict__ att_b2, const float* __restrict__ attWf,
    const float* __restrict__ att_bf)
{
    extern __shared__ float sm[];
    const int b = blockIdx.x;
    const int tid = threadIdx.x;

    // ---- phase 0: gathers + weight caching ----
    for (int f = tid; f < 1280; f += 256) {
        int l = f >> 5, r = f & 31, h = r >> 4, o = r & 15;
        int row = seq[(b * LL + l) * 2 + h];
        float4 v = *(const float4*)(emb_seq + ((size_t)h * VV + row) * EE + o * 4);
        *(float4*)(sm + SM_S + l * 132 + h * 64 + o * 4) = v;
    }
    if (tid < 32) {
        int h = tid >> 4, o = tid & 15;
        int row = item[b * 2 + h];
        float4 v = *(const float4*)(emb_seq + ((size_t)h * VV + row) * EE + o * 4);
        *(float4*)(sm + SM_Q + h * 64 + o * 4) = v;
    }
    for (int i = tid; i < 3200; i += 256) sm[SM_W2 + (i / 40) * 41 + (i % 40)] = attW2[i];
    if (tid >= 32 && tid < 72) {
        sm[SM_WF + tid - 32] = attWf[tid - 32];
        sm[SM_B2 + tid - 32] = att_b2[tid - 32];
    }
    __syncthreads();

    // ---- phase 1: per-b effective weight Weff = Ws + q*Wp; qb = q@Wq + b1 ----
    #pragma unroll 4
    for (int it = 0; it < 40; it++) {
        int i = tid + it * 256;
        int k = i / 80, j = i - k * 80;
        sm[SM_WEFF + k * 88 + j] = g_Ws[i] + sm[SM_Q + k] * g_Wp[i];
    }
    if (tid < 80) {
        float acc = att_b1[tid];
        const float* wq = g_Wq + tid * 128;
        #pragma unroll 8
        for (int k = 0; k < 128; k++) acc = fmaf(sm[SM_Q + k], wq[k], acc);
        sm[SM_QB + tid] = acc;
    }
    __syncthreads();

    // ---- phase 2: layer1 GEMM [40,128]@[128,80], 4x4 register tiles ----
    if (tid < 200) {
        int lg = tid % 10, jg = tid / 10;
        int l0 = lg * 4, j0 = jg * 4;
        float acc[4][4];
        #pragma unroll
        for (int a = 0; a < 4; a++)
            #pragma unroll
            for (int c = 0; c < 4; c++) acc[a][c] = 0.f;
        const float4* S4 = (const float4*)(sm + SM_S);    // row stride 33 f4
        const float4* W4 = (const float4*)(sm + SM_WEFF); // row stride 22 f4
        #pragma unroll 2
        for (int k4 = 0; k4 < 32; k4++) {
            float4 s[4], w[4];
            #pragma unroll
            for (int li = 0; li < 4; li++) s[li] = S4[(l0 + li) * 33 + k4];
            #pragma unroll
            for (int kk = 0; kk < 4; kk++) w[kk] = W4[(k4 * 4 + kk) * 22 + jg];
            #pragma unroll
            for (int li = 0; li < 4; li++) {
                float sx = s[li].x, sy = s[li].y, sz = s[li].z, sww = s[li].w;
                acc[li][0] = fmaf(sx, w[0].x, acc[li][0]);
                acc[li][1] = fmaf(sx, w[0].y, acc[li][1]);
                acc[li][2] = fmaf(sx, w[0].z, acc[li][2]);
                acc[li][3] = fmaf(sx, w[0].w, acc[li][3]);
                acc[li][0] = fmaf(sy, w[1].x, acc[li][0]);
                acc[li][1] = fmaf(sy, w[1].y, acc[li][1]);
                acc[li][2] = fmaf(sy, w[1].z, acc[li][2]);
                acc[li][3] = fmaf(sy, w[1].w, acc[li][3]);
                acc[li][0] = fmaf(sz, w[2].x, acc[li][0]);
                acc[li][1] = fmaf(sz, w[2].y, acc[li][1]);
                acc[li][2] = fmaf(sz, w[2].z, acc[li][2]);
                acc[li][3] = fmaf(sz, w[2].w, acc[li][3]);
                acc[li][0] = fmaf(sww, w[3].x, acc[li][0]);
                acc[li][1] = fmaf(sww, w[3].y, acc[li][1]);
                acc[li][2] = fmaf(sww, w[3].z, acc[li][2]);
                acc[li][3] = fmaf(sww, w[3].w, acc[li][3]);
            }
        }
        #pragma unroll
        for (int li = 0; li < 4; li++)
            #pragma unroll
            for (int jj = 0; jj < 4; jj++) {
                float h = acc[li][jj] + sm[SM_QB + j0 + jj];
                sm[SM_A1 + (l0 + li) * 81 + j0 + jj] = sigmoidf_(h);
            }
    }
    __syncthreads();

    // ---- phase 3: layer2 [40,80]@[80,40] ----
    if (tid < 100) {
        int lg = tid % 10, jg = tid / 10;
        int l0 = lg * 4, j0 = jg * 4;
        float acc[4][4];
        #pragma unroll
        for (int a = 0; a < 4; a++)
            #pragma unroll
            for (int c = 0; c < 4; c++) acc[a][c] = 0.f;
        #pragma unroll 4
        for (int k = 0; k < 80; k++) {
            float a0 = sm[SM_A1 + (l0 + 0) * 81 + k];
            float a1v = sm[SM_A1 + (l0 + 1) * 81 + k];
            float a2v = sm[SM_A1 + (l0 + 2) * 81 + k];
            float a3v = sm[SM_A1 + (l0 + 3) * 81 + k];
            float w0 = sm[SM_W2 + k * 41 + j0 + 0];
            float w1 = sm[SM_W2 + k * 41 + j0 + 1];
            float w2 = sm[SM_W2 + k * 41 + j0 + 2];
            float w3 = sm[SM_W2 + k * 41 + j0 + 3];
            acc[0][0] = fmaf(a0, w0, acc[0][0]); acc[0][1] = fmaf(a0, w1, acc[0][1]);
            acc[0][2] = fmaf(a0, w2, acc[0][2]); acc[0][3] = fmaf(a0, w3, acc[0][3]);
            acc[1][0] = fmaf(a1v, w0, acc[1][0]); acc[1][1] = fmaf(a1v, w1, acc[1][1]);
            acc[1][2] = fmaf(a1v, w2, acc[1][2]); acc[1][3] = fmaf(a1v, w3, acc[1][3]);
            acc[2][0] = fmaf(a2v, w0, acc[2][0]); acc[2][1] = fmaf(a2v, w1, acc[2][1]);
            acc[2][2] = fmaf(a2v, w2, acc[2][2]); acc[2][3] = fmaf(a2v, w3, acc[2][3]);
            acc[3][0] = fmaf(a3v, w0, acc[3][0]); acc[3][1] = fmaf(a3v, w1, acc[3][1]);
            acc[3][2] = fmaf(a3v, w2, acc[3][2]); acc[3][3] = fmaf(a3v, w3, acc[3][3]);
        }
        #pragma unroll
        for (int li = 0; li < 4; li++)
            #pragma unroll
            for (int jj = 0; jj < 4; jj++) {
                float h = acc[li][jj] + sm[SM_B2 + j0 + jj];
                sm[SM_A2 + (l0 + li) * 41 + j0 + jj] = sigmoidf_(h);
            }
    }
    __syncthreads();

    // ---- phase 4: logits + mask ----
    if (tid < 40) {
        float acc = att_bf[0];
        #pragma unroll 8
        for (int k = 0; k < 40; k++) acc = fmaf(sm[SM_A2 + tid * 41 + k], sm[SM_WF + k], acc);
        int m0 = seq[(b * LL + tid) * 2];
        sm[SM_LOG + tid] = (m0 != 0) ? acc : -4294967295.0f;
    }
    __syncthreads();

    // ---- phase 5: softmax over 40 ----
    if (tid < 32) {
        float v = sm[SM_LOG + tid];
        if (tid < 8) v = fmaxf(v, sm[SM_LOG + 32 + tid]);
        #pragma unroll
        for (int o = 16; o > 0; o >>= 1) v = fmaxf(v, __shfl_xor_sync(0xffffffffu, v, o));
        if (tid == 0) sm[SM_RED] = v;
    }
    __syncthreads();
    if (tid < 40) sm[SM_ATT + tid] = __expf(sm[SM_LOG + tid] - sm[SM_RED]);
    __syncthreads();
    if (tid < 32) {
        float v = sm[SM_ATT + tid];
        if (tid < 8) v += sm[SM_ATT + 32 + tid];
        #pragma unroll
        for (int o = 16; o > 0; o >>= 1) v += __shfl_xor_sync(0xffffffffu, v, o);
        if (tid == 0) sm[SM_RED + 1] = 1.f / v;
    }
    __syncthreads();

    // ---- phase 6: attention pooling + assemble x[456] into g_X ----
    float* xb = g_X + (size_t)b * ALLD;
    if (tid < 128) {
        float inv = sm[SM_RED + 1];
        float u = 0.f;
        #pragma unroll 8
        for (int l = 0; l < 40; l++) u = fmaf(sm[SM_ATT + l], sm[SM_S + l * 132 + tid], u);
        xb[tid] = u * inv;
        xb[128 + tid] = sm[SM_Q + tid];
    }
    if (tid >= 128 && tid < 136) xb[256 + (tid - 128)] = dense[b * 8 + (tid - 128)];
    if (tid >= 64) {
        int t = tid - 64, i = t >> 6, e = t & 63;
        int row = sparse[b * 3 + i];
        xb[264 + i * 64 + e] = emb_sp[((size_t)i * VV + row) * EE + e];
    }
}

// ---------------- FFN: 64 batch rows per CTA, weights staged in smem ----------------
#define FS_XS  0        // 64 x 461
#define FS_WC  29504    // 80 x 157 (K-chunk of W1fT)
#define FS_F1  42064    // 64 x 81
#define FS_W2  47248    // 80 x 41
#define FS_F2  50528    // 64 x 41
#define FS_A1P 53152    // 80
#define FS_B2P 53232    // 40
#define FS_A2P 53272    // 40
#define FS_WO  53312    // 40
#define SM_FFN_FLOATS 53352

__global__ void __launch_bounds__(256, 1) din_ffn(
    const float* __restrict__ a1, const float* __restrict__ W2,
    const float* __restrict__ b2, const float* __restrict__ a2,
    const float* __restrict__ outW, const float* __restrict__ outB,
    float* __restrict__ out)
{
    extern __shared__ float sm[];
    const int tid = threadIdx.x;
    const int b0 = blockIdx.x * 64;

    for (int i = tid; i < 64 * 456; i += 256) {
        int r = i / 456, c = i - r * 456;
        sm[FS_XS + r * 461 + c] = g_X[(size_t)(b0 + r) * 456 + c];
    }
    for (int i = tid; i < 3200; i += 256) sm[FS_W2 + (i / 40) * 41 + (i % 40)] = W2[i];
    if (tid < 80) sm[FS_A1P + tid] = a1[tid];
    if (tid >= 80 && tid < 120) sm[FS_B2P + tid - 80] = b2[tid - 80];
    if (tid >= 120 && tid < 160) sm[FS_A2P + tid - 120] = a2[tid - 120];
    if (tid >= 160 && tid < 200) sm[FS_WO + tid - 160] = outW[tid - 160];

    // FFN1: [64,456]@[456,80], chunked K in smem, 4b x 5j per thread
    int bg = tid / 16, jg = tid % 16;
    int bb = bg * 4, j0 = jg * 5;
    float acc[4][5];
    #pragma unroll
    for (int a = 0; a < 4; a++)
        #pragma unroll
        for (int c = 0; c < 5; c++) acc[a][c] = 0.f;

    for (int cch = 0; cch < 3; cch++) {
        __syncthreads();
        for (int i = tid; i < 80 * 152; i += 256) {
            int j = i / 152, kk = i - j * 152;
            sm[FS_WC + j * 157 + kk] = g_W1fT[j * 456 + cch * 152 + kk];
        }
        __syncthreads();
        #pragma unroll 4
        for (int kk = 0; kk < 152; kk++) {
            int k = cch * 152 + kk;
            float x0 = sm[FS_XS + (bb + 0) * 461 + k];
            float x1 = sm[FS_XS + (bb + 1) * 461 + k];
            float x2 = sm[FS_XS + (bb + 2) * 461 + k];
            float x3 = sm[FS_XS + (bb + 3) * 461 + k];
            #pragma unroll
            for (int jj = 0; jj < 5; jj++) {
                float w = sm[FS_WC + (j0 + jj) * 157 + kk];
                acc[0][jj] = fmaf(x0, w, acc[0][jj]);
                acc[1][jj] = fmaf(x1, w, acc[1][jj]);
                acc[2][jj] = fmaf(x2, w, acc[2][jj]);
                acc[3][jj] = fmaf(x3, w, acc[3][jj]);
            }
        }
    }
    #pragma unroll
    for (int bi = 0; bi < 4; bi++)
        #pragma unroll
        for (int jj = 0; jj < 5; jj++) {
            int j = j0 + jj;
            float h = acc[bi][jj] + g_b1f[j];
            sm[FS_F1 + (bb + bi) * 81 + j] = h > 0.f ? h : sm[FS_A1P + j] * h;
        }
    __syncthreads();

    // FFN2: [64,80]@[80,40]
    if (tid < 160) {
        int bg2 = tid / 10, jg2 = tid % 10;
        int bb2 = bg2 * 4, j02 = jg2 * 4;
        float acc2[4][4];
        #pragma unroll
        for (int a = 0; a < 4; a++)
            #pragma unroll
            for (int c = 0; c < 4; c++) acc2[a][c] = 0.f;
        #pragma unroll 4
        for (int k = 0; k < 80; k++) {
            float x0 = sm[FS_F1 + (bb2 + 0) * 81 + k];
            float x1 = sm[FS_F1 + (bb2 + 1) * 81 + k];
            float x2 = sm[FS_F1 + (bb2 + 2) * 81 + k];
            float x3 = sm[FS_F1 + (bb2 + 3) * 81 + k];
            float w0 = sm[FS_W2 + k * 41 + j02 + 0];
            float w1 = sm[FS_W2 + k * 41 + j02 + 1];
            float w2 = sm[FS_W2 + k * 41 + j02 + 2];
            float w3 = sm[FS_W2 + k * 41 + j02 + 3];
            acc2[0][0] = fmaf(x0, w0, acc2[0][0]); acc2[0][1] = fmaf(x0, w1, acc2[0][1]);
            acc2[0][2] = fmaf(x0, w2, acc2[0][2]); acc2[0][3] = fmaf(x0, w3, acc2[0][3]);
            acc2[1][0] = fmaf(x1, w0, acc2[1][0]); acc2[1][1] = fmaf(x1, w1, acc2[1][1]);
            acc2[1][2] = fmaf(x1, w2, acc2[1][2]); acc2[1][3] = fmaf(x1, w3, acc2[1][3]);
            acc2[2][0] = fmaf(x2, w0, acc2[2][0]); acc2[2][1] = fmaf(x2, w1, acc2[2][1]);
            acc2[2][2] = fmaf(x2, w2, acc2[2][2]); acc2[2][3] = fmaf(x2, w3, acc2[2][3]);
            acc2[3][0] = fmaf(x3, w0, acc2[3][0]); acc2[3][1] = fmaf(x3, w1, acc2[3][1]);
            acc2[3][2] = fmaf(x3, w2, acc2[3][2]); acc2[3][3] = fmaf(x3, w3, acc2[3][3]);
        }
        #pragma unroll
        for (int bi = 0; bi < 4; bi++)
            #pragma unroll
            for (int jj = 0; jj < 4; jj++) {
                int j = j02 + jj;
                float h = acc2[bi][jj] + sm[FS_B2P + j];
                sm[FS_F2 + (bb2 + bi) * 41 + j] = h > 0.f ? h : sm[FS_A2P + j] * h;
            }
    }
    __syncthreads();

    if (tid < 64) {
        float acc3 = outB[0];
        #pragma unroll 8
        for (int k = 0; k < 40; k++) acc3 = fmaf(sm[FS_F2 + tid * 41 + k], sm[FS_WO + k], acc3);
        out[b0 + tid] = sigmoidf_(acc3);
    }
}

// ---------------- launch ----------------
extern "C" void kernel_launch(void* const* d_in, const int* in_sizes, int n_in,
                              void* d_out, int out_size)
{
    const float* dense = (const float*)d_in[0];
    const int*   sparse = (const int*)d_in[1];
    const int*   seq = (const int*)d_in[2];
    const int*   item = (const int*)d_in[3];
    const float* emb_sp = (const float*)d_in[4];
    const float* embsq = (const float*)d_in[5];
    const float* attW1 = (const float*)d_in[6];
    const float* attb1 = (const float*)d_in[7];
    const float* attW2 = (const float*)d_in[8];
    const float* attb2 = (const float*)d_in[9];
    const float* attWf = (const float*)d_in[10];
    const float* attbf = (const float*)d_in[11];
    const float* gam = (const float*)d_in[12];
    const float* bet = (const float*)d_in[13];
    const float* mu = (const float*)d_in[14];
    const float* var = (const float*)d_in[15];
    const float* fW1 = (const float*)d_in[16];
    const float* fb1 = (const float*)d_in[17];
    const float* fa1 = (const float*)d_in[18];
    const float* fW2 = (const float*)d_in[19];
    const float* fb2 = (const float*)d_in[20];
    const float* fa2 = (const float*)d_in[21];
    const float* oW = (const float*)d_in[22];
    const float* oB = (const float*)d_in[23];
    float* out = (float*)d_out;

    cudaFuncSetAttribute(din_main, cudaFuncAttributeMaxDynamicSharedMemorySize, SM_MAIN_FLOATS * 4);
    cudaFuncSetAttribute(din_ffn, cudaFuncAttributeMaxDynamicSharedMemorySize, SM_FFN_FLOATS * 4);

    din_prep<<<183, 256>>>(attW1, fW1, fb1, gam, bet, mu, var);
    din_main<<<BB, 256, SM_MAIN_FLOATS * 4>>>(dense, sparse, seq, item, emb_sp, embsq,
                                              attb1, attW2, attb2, attWf, attbf);
    din_ffn<<<BB / 64, 256, SM_FFN_FLOATS * 4>>>(fa1, fW2, fb2, fa2, oW, oB, out);
}

// round 3
// speedup vs baseline: 1.9809x; 1.9809x over previous
#include <cuda_runtime.h>

#define BB   8192
#define LL   40
#define VV   100000
#define EE   64
#define ALLD 456

typedef unsigned long long ull;

// ---------------- device scratch ----------------
__device__ float g_WqT[128 * 80];    // [k][j] = W1[k][j] + W1[256+k][j]
__device__ float g_Ws[128 * 80];     // [k][j] = W1[128+k][j] - W1[256+k][j]
__device__ float g_Wp[128 * 80];     // [k][j] = W1[384+k][j]
__device__ float g_W1f[456 * 80];    // [i][j] = ffn_W1[i][j] * bn_scale[i]
__device__ float g_b1f[80];
__device__ float g_QB[(size_t)BB * 80];   // per-b attention layer1 q-part + bias
__device__ float g_X[(size_t)BB * ALLD];

__device__ __forceinline__ float sigmoidf_(float x) { return 1.f / (1.f + __expf(-x)); }
__device__ __forceinline__ ull pack2_(float x, float y) {
    ull r; asm("mov.b64 %0, {%1,%2};" : "=l"(r) : "f"(x), "f"(y)); return r;
}
__device__ __forceinline__ void unpack2_(ull v, float& x, float& y) {
    asm("mov.b64 {%0,%1}, %2;" : "=f"(x), "=f"(y) : "l"(v));
}
#define FFMA2(d, a, b, c) asm("fma.rn.f32x2 %0, %1, %2, %3;" : "=l"(d) : "l"(a), "l"(b), "l"(c))

// ---------------- prep: fold weights ----------------
__global__ void din_prep(const float* __restrict__ attW1,
                         const float* __restrict__ ffnW1,
                         const float* __restrict__ ffnb1,
                         const float* __restrict__ gam,
                         const float* __restrict__ bet,
                         const float* __restrict__ mu,
                         const float* __restrict__ var)
{
    int idx = blockIdx.x * 256 + threadIdx.x;
    if (idx < 10240) {
        float wc = attW1[256 * 80 + idx];
        g_WqT[idx] = attW1[idx] + wc;
        g_Ws[idx]  = attW1[128 * 80 + idx] - wc;
        g_Wp[idx]  = attW1[384 * 80 + idx];
    } else if (idx < 46720) {
        int t = idx - 10240;
        int i = t / 80;
        g_W1f[t] = ffnW1[t] * (gam[i] * rsqrtf(var[i] + 1e-3f));
    } else if (idx < 49280) {
        int t = idx - 46720;
        int j = t >> 5, lane = t & 31;
        float acc = 0.f;
        for (int i = lane; i < 456; i += 32) {
            float sc = gam[i] * rsqrtf(var[i] + 1e-3f);
            acc += (bet[i] - mu[i] * sc) * ffnW1[i * 80 + j];
        }
        #pragma unroll
        for (int o = 16; o > 0; o >>= 1) acc += __shfl_xor_sync(0xffffffffu, acc, o);
        if (lane == 0) g_b1f[j] = ffnb1[j] + acc;
    }
}

// ---------------- qb: qb[b][j] = b1[j] + sum_k q[b][k] * WqT[k][j] ----------------
#define QB_W 0        // 128 x 80
#define QB_Q 10240    // 64 x 132
#define QB_SMEM ((10240 + 64 * 132) * 4)

__global__ void __launch_bounds__(256) din_qb(
    const int* __restrict__ item, const float* __restrict__ emb_seq,
    const float* __restrict__ att_b1)
{
    extern __shared__ float sq[];
    const int tid = threadIdx.x;
    const int b0 = blockIdx.x * 64;

    for (int i = tid; i < 2560; i += 256)
        ((float4*)(sq + QB_W))[i] = ((const float4*)g_WqT)[i];
    for (int f = tid; f < 2048; f += 256) {
        int bi = f >> 5, r = f & 31, h = r >> 4, o = r & 15;
        int row = item[(b0 + bi) * 2 + h];
        float4 v = *(const float4*)(emb_seq + ((size_t)h * VV + row) * EE + o * 4);
        *(float4*)(sq + QB_Q + bi * 132 + h * 64 + o * 4) = v;
    }
    __syncthreads();

    int jg = tid & 15, bg = tid >> 4;
    int j0 = jg * 5, bb = bg * 4;
    float acc[4][5];
    #pragma unroll
    for (int bi = 0; bi < 4; bi++)
        #pragma unroll
        for (int jj = 0; jj < 5; jj++) acc[bi][jj] = att_b1[j0 + jj];
    #pragma unroll 4
    for (int k = 0; k < 128; k++) {
        float w[5];
        #pragma unroll
        for (int jj = 0; jj < 5; jj++) w[jj] = sq[QB_W + k * 80 + j0 + jj];
        #pragma unroll
        for (int bi = 0; bi < 4; bi++) {
            float q = sq[QB_Q + (bb + bi) * 132 + k];
            #pragma unroll
            for (int jj = 0; jj < 5; jj++) acc[bi][jj] = fmaf(q, w[jj], acc[bi][jj]);
        }
    }
    #pragma unroll
    for (int bi = 0; bi < 4; bi++)
        #pragma unroll
        for (int jj = 0; jj < 5; jj++)
            g_QB[(size_t)(b0 + bb + bi) * 80 + j0 + jj] = acc[bi][jj];
}

// ---------------- main: attention per batch element ----------------
// smem layout (floats)
#define SM_S2   0        // 40 rows x 130 pairs (value duplicated), stride 260 floats
#define SM_WEFF 10400    // 128 x 88   (overlaid by A1dup after phase2)
#define SM_A1   10400    // 40 rows x 82 pairs
#define SM_W2   21664    // 80 x 44
#define SM_A2   25184    // 40 x 44
#define SM_Q    26944    // 128
#define SM_QB   27072    // 80
#define SM_WF   27152    // 40
#define SM_B2   27192    // 40
#define SM_LOG  27232    // 40
#define SM_ATT  27272    // 40
#define SM_MSK  27312    // 40
#define SM_RED  27352    // 2
#define SM_MAIN_FLOATS 27354

__global__ void __launch_bounds__(256, 2) din_main(
    const float* __restrict__ dense, const int* __restrict__ sparse,
    const int* __restrict__ seq, const int* __restrict__ item,
    const float* __restrict__ emb_sp, const float* __restrict__ emb_seq,
    const float* __restrict__ attW2, const float* __restrict__ att_b2,
    const float* __restrict__ attWf, const float* __restrict__ att_bf)
{
    extern __shared__ float sm[];
    const int b = blockIdx.x;
    const int tid = threadIdx.x;

    // ---- phase 0: gathers + staging ----
    for (int f = tid; f < 1280; f += 256) {
        int l = f >> 5, r = f & 31, h = r >> 4, o = r & 15;
        int row = seq[(b * LL + l) * 2 + h];
        float4 v = *(const float4*)(emb_seq + ((size_t)h * VV + row) * EE + o * 4);
        float* p = sm + SM_S2 + (l * 130 + h * 64 + o * 4) * 2;
        *(float4*)(p)     = make_float4(v.x, v.x, v.y, v.y);
        *(float4*)(p + 4) = make_float4(v.z, v.z, v.w, v.w);
        if (r == 0) sm[SM_MSK + l] = (row != 0) ? 1.f : 0.f;
    }
    if (tid < 32) {
        int h = tid >> 4, o = tid & 15;
        int row = item[b * 2 + h];
        float4 v = *(const float4*)(emb_seq + ((size_t)h * VV + row) * EE + o * 4);
        *(float4*)(sm + SM_Q + h * 64 + o * 4) = v;
    }
    for (int i = tid; i < 800; i += 256) {
        int r = i / 10, c = (i % 10) * 4;
        *(float4*)(sm + SM_W2 + r * 44 + c) = ((const float4*)attW2)[i];
    }
    if (tid < 80) sm[SM_QB + tid] = g_QB[(size_t)b * 80 + tid];
    if (tid >= 96 && tid < 136) sm[SM_WF + tid - 96] = attWf[tid - 96];
    if (tid >= 136 && tid < 176) sm[SM_B2 + tid - 136] = att_b2[tid - 136];
    __syncthreads();

    // ---- phase 1: Weff[k][j] = Ws + q[k]*Wp ----
    #pragma unroll
    for (int it = 0; it < 10; it++) {
        int pf4 = tid + it * 256;           // 2560 float4s
        int k = pf4 / 20, jf = pf4 % 20;
        float4 ws = ((const float4*)g_Ws)[pf4];
        float4 wp = ((const float4*)g_Wp)[pf4];
        float qk = sm[SM_Q + k];
        float4 o;
        o.x = fmaf(qk, wp.x, ws.x); o.y = fmaf(qk, wp.y, ws.y);
        o.z = fmaf(qk, wp.z, ws.z); o.w = fmaf(qk, wp.w, ws.w);
        *(float4*)(sm + SM_WEFF + k * 88 + jf * 4) = o;
    }
    __syncthreads();

    // ---- phase 2: layer1 [40,128]@[128,80] in f32x2 ----
    ull acc1[5][2];
    int jg = tid % 20, lg = tid / 20;
    int j0 = jg * 4, l0 = lg * 5;
    if (tid < 160) {
        #pragma unroll
        for (int li = 0; li < 5; li++) { acc1[li][0] = 0ull; acc1[li][1] = 0ull; }
        #pragma unroll 4
        for (int k = 0; k < 128; k++) {
            ulonglong2 w = *(const ulonglong2*)(sm + SM_WEFF + k * 88 + j0);
            #pragma unroll
            for (int li = 0; li < 5; li++) {
                ull s2 = *(const ull*)(sm + SM_S2 + ((l0 + li) * 130 + k) * 2);
                FFMA2(acc1[li][0], s2, w.x, acc1[li][0]);
                FFMA2(acc1[li][1], s2, w.y, acc1[li][1]);
            }
        }
    }
    __syncthreads();   // all Weff reads done before A1dup overlay writes
    if (tid < 160) {
        #pragma unroll
        for (int li = 0; li < 5; li++) {
            int l = l0 + li;
            #pragma unroll
            for (int jp = 0; jp < 2; jp++) {
                float x, y; unpack2_(acc1[li][jp], x, y);
                int ja = j0 + jp * 2;
                float h0 = sigmoidf_(x + sm[SM_QB + ja]);
                float h1 = sigmoidf_(y + sm[SM_QB + ja + 1]);
                *(ull*)(sm + SM_A1 + (l * 82 + ja) * 2)     = pack2_(h0, h0);
                *(ull*)(sm + SM_A1 + (l * 82 + ja + 1) * 2) = pack2_(h1, h1);
            }
        }
    }
    __syncthreads();

    // ---- phase 3: layer2 [40,80]@[80,40] in f32x2 ----
    if (tid < 160) {
        int jg3 = tid % 20, lg3 = tid / 20;
        int j03 = jg3 * 2, l03 = lg3 * 5;
        ull acc2[5];
        #pragma unroll
        for (int li = 0; li < 5; li++) acc2[li] = 0ull;
        #pragma unroll 4
        for (int k = 0; k < 80; k++) {
            ull w = *(const ull*)(sm + SM_W2 + k * 44 + j03);
            #pragma unroll
            for (int li = 0; li < 5; li++) {
                ull a = *(const ull*)(sm + SM_A1 + ((l03 + li) * 82 + k) * 2);
                FFMA2(acc2[li], a, w, acc2[li]);
            }
        }
        #pragma unroll
        for (int li = 0; li < 5; li++) {
            float x, y; unpack2_(acc2[li], x, y);
            int l = l03 + li;
            sm[SM_A2 + l * 44 + j03]     = sigmoidf_(x + sm[SM_B2 + j03]);
            sm[SM_A2 + l * 44 + j03 + 1] = sigmoidf_(y + sm[SM_B2 + j03 + 1]);
        }
    }
    __syncthreads();

    // ---- phase 4: logits + mask ----
    if (tid < 40) {
        float acc = att_bf[0];
        #pragma unroll 8
        for (int k = 0; k < 40; k++) acc = fmaf(sm[SM_A2 + tid * 44 + k], sm[SM_WF + k], acc);
        sm[SM_LOG + tid] = (sm[SM_MSK + tid] != 0.f) ? acc : -4294967295.0f;
    }
    __syncthreads();

    // ---- phase 5: softmax over 40 ----
    if (tid < 32) {
        float v = sm[SM_LOG + tid];
        if (tid < 8) v = fmaxf(v, sm[SM_LOG + 32 + tid]);
        #pragma unroll
        for (int o = 16; o > 0; o >>= 1) v = fmaxf(v, __shfl_xor_sync(0xffffffffu, v, o));
        if (tid == 0) sm[SM_RED] = v;
    }
    __syncthreads();
    if (tid < 40) sm[SM_ATT + tid] = __expf(sm[SM_LOG + tid] - sm[SM_RED]);
    __syncthreads();
    if (tid < 32) {
        float v = sm[SM_ATT + tid];
        if (tid < 8) v += sm[SM_ATT + 32 + tid];
        #pragma unroll
        for (int o = 16; o > 0; o >>= 1) v += __shfl_xor_sync(0xffffffffu, v, o);
        if (tid == 0) sm[SM_RED + 1] = 1.f / v;
    }
    __syncthreads();

    // ---- phase 6: pooling + assemble x[456] ----
    float* xb = g_X + (size_t)b * ALLD;
    if (tid < 128) {
        float inv = sm[SM_RED + 1];
        float u = 0.f;
        #pragma unroll 8
        for (int l = 0; l < 40; l++) u = fmaf(sm[SM_ATT + l], sm[SM_S2 + (l * 130 + tid) * 2], u);
        xb[tid] = u * inv;
        xb[128 + tid] = sm[SM_Q + tid];
    }
    if (tid >= 128 && tid < 136) xb[256 + (tid - 128)] = dense[b * 8 + (tid - 128)];
    if (tid >= 64) {
        int t = tid - 64, i = t >> 6, e = t & 63;
        int row = sparse[b * 3 + i];
        xb[264 + i * 64 + e] = emb_sp[((size_t)i * VV + row) * EE + e];
    }
}

// ---------------- FFN: 64 batch rows per CTA ----------------
#define FS_XS   0        // 64 x 460
#define FS_WCT  29440    // 152 x 80 (K-chunk of g_W1f, [k][j])
#define FS_F1   41600    // 64 x 81
#define FS_W2   46784    // 80 x 44
#define FS_F2   50304    // 64 x 41
#define FS_B1F  52928    // 80
#define FS_A1P  53008    // 80
#define FS_B2P  53088    // 40
#define FS_A2P  53128    // 40
#define FS_WO   53168    // 40
#define SM_FFN_FLOATS 53208

__global__ void __launch_bounds__(256, 1) din_ffn(
    const float* __restrict__ a1, const float* __restrict__ W2,
    const float* __restrict__ b2, const float* __restrict__ a2,
    const float* __restrict__ outW, const float* __restrict__ outB,
    float* __restrict__ out)
{
    extern __shared__ float sm[];
    const int tid = threadIdx.x;
    const int b0 = blockIdx.x * 64;

    const float4* X4 = (const float4*)g_X;
    for (int i = tid; i < 64 * 114; i += 256) {
        int r = i / 114, c = i % 114;
        *(float4*)(sm + FS_XS + r * 460 + c * 4) = X4[(size_t)(b0 + r) * 114 + c];
    }
    for (int i = tid; i < 800; i += 256) {
        int r = i / 10, c = (i % 10) * 4;
        *(float4*)(sm + FS_W2 + r * 44 + c) = ((const float4*)W2)[i];
    }
    if (tid < 80)  sm[FS_B1F + tid] = g_b1f[tid];
    if (tid >= 80 && tid < 160)  sm[FS_A1P + tid - 80] = a1[tid - 80];
    if (tid >= 160 && tid < 200) sm[FS_B2P + tid - 160] = b2[tid - 160];
    if (tid >= 200 && tid < 240) sm[FS_A2P + tid - 200] = a2[tid - 200];
    if (tid < 40) sm[FS_WO + tid] = outW[tid];   // distinct region; ok with B1F write set

    // FFN1: [64,456]@[456,80] in f32x2, K chunks of 152
    int jg = tid % 10, bg = tid / 10;      // 160 active threads
    int j0 = jg * 8, bb = bg * 4;
    ull acc[4][4];
    #pragma unroll
    for (int bi = 0; bi < 4; bi++)
        #pragma unroll
        for (int jp = 0; jp < 4; jp++) acc[bi][jp] = 0ull;

    const float4* W1f4 = (const float4*)g_W1f;
    for (int cch = 0; cch < 3; cch++) {
        __syncthreads();
        for (int i = tid; i < 3040; i += 256)
            *(float4*)(sm + FS_WCT + i * 4) = W1f4[cch * 3040 + i];
        __syncthreads();
        if (tid < 160) {
            #pragma unroll 2
            for (int kk = 0; kk < 152; kk++) {
                int k = cch * 152 + kk;
                ull w[4];
                #pragma unroll
                for (int jp = 0; jp < 4; jp++)
                    w[jp] = *(const ull*)(sm + FS_WCT + kk * 80 + j0 + jp * 2);
                #pragma unroll
                for (int bi = 0; bi < 4; bi++) {
                    float xv = sm[FS_XS + (bb + bi) * 460 + k];
                    ull xs = pack2_(xv, xv);
                    #pragma unroll
                    for (int jp = 0; jp < 4; jp++) FFMA2(acc[bi][jp], xs, w[jp], acc[bi][jp]);
                }
            }
        }
    }
    if (tid < 160) {
        #pragma unroll
        for (int bi = 0; bi < 4; bi++)
            #pragma unroll
            for (int jp = 0; jp < 4; jp++) {
                float x, y; unpack2_(acc[bi][jp], x, y);
                int j = j0 + jp * 2;
                float h0 = x + sm[FS_B1F + j];
                float h1 = y + sm[FS_B1F + j + 1];
                h0 = h0 > 0.f ? h0 : sm[FS_A1P + j] * h0;
                h1 = h1 > 0.f ? h1 : sm[FS_A1P + j + 1] * h1;
                sm[FS_F1 + (bb + bi) * 81 + j] = h0;
                sm[FS_F1 + (bb + bi) * 81 + j + 1] = h1;
            }
    }
    __syncthreads();

    // FFN2: [64,80]@[80,40]
    if (tid < 160) {
        int bg2 = tid / 10, jg2 = tid % 10;
        int bb2 = bg2 * 4, j02 = jg2 * 4;
        float acc2[4][4];
        #pragma unroll
        for (int a = 0; a < 4; a++)
            #pragma unroll
            for (int c = 0; c < 4; c++) acc2[a][c] = 0.f;
        #pragma unroll 4
        for (int k = 0; k < 80; k++) {
            float x0 = sm[FS_F1 + (bb2 + 0) * 81 + k];
            float x1 = sm[FS_F1 + (bb2 + 1) * 81 + k];
            float x2 = sm[FS_F1 + (bb2 + 2) * 81 + k];
            float x3 = sm[FS_F1 + (bb2 + 3) * 81 + k];
            float w0 = sm[FS_W2 + k * 44 + j02 + 0];
            float w1 = sm[FS_W2 + k * 44 + j02 + 1];
            float w2 = sm[FS_W2 + k * 44 + j02 + 2];
            float w3 = sm[FS_W2 + k * 44 + j02 + 3];
            acc2[0][0] = fmaf(x0, w0, acc2[0][0]); acc2[0][1] = fmaf(x0, w1, acc2[0][1]);
            acc2[0][2] = fmaf(x0, w2, acc2[0][2]); acc2[0][3] = fmaf(x0, w3, acc2[0][3]);
            acc2[1][0] = fmaf(x1, w0, acc2[1][0]); acc2[1][1] = fmaf(x1, w1, acc2[1][1]);
            acc2[1][2] = fmaf(x1, w2, acc2[1][2]); acc2[1][3] = fmaf(x1, w3, acc2[1][3]);
            acc2[2][0] = fmaf(x2, w0, acc2[2][0]); acc2[2][1] = fmaf(x2, w1, acc2[2][1]);
            acc2[2][2] = fmaf(x2, w2, acc2[2][2]); acc2[2][3] = fmaf(x2, w3, acc2[2][3]);
            acc2[3][0] = fmaf(x3, w0, acc2[3][0]); acc2[3][1] = fmaf(x3, w1, acc2[3][1]);
            acc2[3][2] = fmaf(x3, w2, acc2[3][2]); acc2[3][3] = fmaf(x3, w3, acc2[3][3]);
        }
        #pragma unroll
        for (int bi = 0; bi < 4; bi++)
            #pragma unroll
            for (int jj = 0; jj < 4; jj++) {
                int j = j02 + jj;
                float h = acc2[bi][jj] + sm[FS_B2P + j];
                sm[FS_F2 + (bb2 + bi) * 41 + j] = h > 0.f ? h : sm[FS_A2P + j] * h;
            }
    }
    __syncthreads();

    if (tid < 64) {
        float acc3 = outB[0];
        #pragma unroll 8
        for (int k = 0; k < 40; k++) acc3 = fmaf(sm[FS_F2 + tid * 41 + k], sm[FS_WO + k], acc3);
        out[b0 + tid] = sigmoidf_(acc3);
    }
}

// ---------------- launch ----------------
extern "C" void kernel_launch(void* const* d_in, const int* in_sizes, int n_in,
                              void* d_out, int out_size)
{
    const float* dense = (const float*)d_in[0];
    const int*   sparse = (const int*)d_in[1];
    const int*   seq = (const int*)d_in[2];
    const int*   item = (const int*)d_in[3];
    const float* emb_sp = (const float*)d_in[4];
    const float* embsq = (const float*)d_in[5];
    const float* attW1 = (const float*)d_in[6];
    const float* attb1 = (const float*)d_in[7];
    const float* attW2 = (const float*)d_in[8];
    const float* attb2 = (const float*)d_in[9];
    const float* attWf = (const float*)d_in[10];
    const float* attbf = (const float*)d_in[11];
    const float* gam = (const float*)d_in[12];
    const float* bet = (const float*)d_in[13];
    const float* mu = (const float*)d_in[14];
    const float* var = (const float*)d_in[15];
    const float* fW1 = (const float*)d_in[16];
    const float* fb1 = (const float*)d_in[17];
    const float* fa1 = (const float*)d_in[18];
    const float* fW2 = (const float*)d_in[19];
    const float* fb2 = (const float*)d_in[20];
    const float* fa2 = (const float*)d_in[21];
    const float* oW = (const float*)d_in[22];
    const float* oB = (const float*)d_in[23];
    float* out = (float*)d_out;

    cudaFuncSetAttribute(din_qb, cudaFuncAttributeMaxDynamicSharedMemorySize, QB_SMEM);
    cudaFuncSetAttribute(din_main, cudaFuncAttributeMaxDynamicSharedMemorySize, SM_MAIN_FLOATS * 4);
    cudaFuncSetAttribute(din_ffn, cudaFuncAttributeMaxDynamicSharedMemorySize, SM_FFN_FLOATS * 4);

    din_prep<<<193, 256>>>(attW1, fW1, fb1, gam, bet, mu, var);
    din_qb<<<BB / 64, 256, QB_SMEM>>>(item, embsq, attb1);
    din_main<<<BB, 256, SM_MAIN_FLOATS * 4>>>(dense, sparse, seq, item, emb_sp, embsq,
                                              attW2, attb2, attWf, attbf);
    din_ffn<<<BB / 64, 256, SM_FFN_FLOATS * 4>>>(fa1, fW2, fb2, fa2, oW, oB, out);
}

// round 6
// speedup vs baseline: 3.0691x; 1.5494x over previous
#include <cuda_runtime.h>
#include <cuda_bf16.h>
#include <cstdint>

#define BB   8192
#define LL   40
#define VV   100000
#define ALLD 456

typedef unsigned long long ull;

// ---------------- device scratch ----------------
__device__ float g_W1f[456 * 80];    // BN-folded FFN W1, [i][j]
__device__ float g_b1f[80];
__device__ float g_X[(size_t)BB * ALLD];
__device__ float g_LOG[(size_t)BB * LL];
__device__ __align__(16) unsigned char g_Wb[80 * 384 * 2];   // att layer1 B: [n][k] bf16 row-major
__device__ __align__(16) unsigned char g_W2b[40 * 80 * 2];   // att layer2 B: [n][k] bf16 row-major

__device__ __forceinline__ float sigmoidf_(float x) { return 1.f / (1.f + __expf(-x)); }
__device__ __forceinline__ ull pack2_(float x, float y) {
    ull r; asm("mov.b64 %0, {%1,%2};" : "=l"(r) : "f"(x), "f"(y)); return r;
}
__device__ __forceinline__ void unpack2_(ull v, float& x, float& y) {
    asm("mov.b64 {%0,%1}, %2;" : "=f"(x), "=f"(y) : "l"(v));
}
#define FFMA2(d, a, b, c) asm("fma.rn.f32x2 %0, %1, %2, %3;" : "=l"(d) : "l"(a), "l"(b), "l"(c))

__device__ __forceinline__ uint32_t bf2_(float lo, float hi) {
    uint32_t r; asm("cvt.rn.bf16x2.f32 %0, %1, %2;" : "=r"(r) : "f"(hi), "f"(lo)); return r;
}
__device__ __forceinline__ uint32_t smem_u32_(const void* p) {
    uint32_t a; asm("{ .reg .u64 t; cvta.to.shared.u64 t, %1; cvt.u32.u64 %0, t; }" : "=r"(a) : "l"(p));
    return a;
}
#define LDSM4(r0, r1, r2, r3, a) \
    asm volatile("ldmatrix.sync.aligned.m8n8.x4.shared.b16 {%0,%1,%2,%3}, [%4];" \
                 : "=r"(r0), "=r"(r1), "=r"(r2), "=r"(r3) : "r"(a))
#define LDSM2(r0, r1, a) \
    asm volatile("ldmatrix.sync.aligned.m8n8.x2.shared.b16 {%0,%1}, [%2];" \
                 : "=r"(r0), "=r"(r1) : "r"(a))
#define MMA16816(c, a0, a1, a2, a3, b0, b1) \
    asm volatile("mma.sync.aligned.m16n8k16.row.col.f32.bf16.bf16.f32 " \
                 "{%0,%1,%2,%3}, {%4,%5,%6,%7}, {%8,%9}, {%0,%1,%2,%3};" \
                 : "+f"((c)[0]), "+f"((c)[1]), "+f"((c)[2]), "+f"((c)[3]) \
                 : "r"(a0), "r"(a1), "r"(a2), "r"(a3), "r"(b0), "r"(b1))

// ---------------- prep: fold weights + build bf16 B operands ----------------
// layer1 k layout: [0,128)=s coeff (Wb-Wc), [128,256)=q*s coeff (Wd), [256,384)=q coeff (Wa+Wc)
__global__ void din_prep(const float* __restrict__ attW1,
                         const float* __restrict__ attW2,
                         const float* __restrict__ ffnW1,
                         const float* __restrict__ ffnb1,
                         const float* __restrict__ gam,
                         const float* __restrict__ bet,
                         const float* __restrict__ mu,
                         const float* __restrict__ var)
{
    int idx = blockIdx.x * 256 + threadIdx.x;
    if (idx < 36480) {
        int i = idx / 80;
        g_W1f[idx] = ffnW1[idx] * (gam[i] * rsqrtf(var[i] + 1e-3f));
    } else if (idx < 39040) {
        int t = idx - 36480;
        int j = t >> 5, lane = t & 31;
        float acc = 0.f;
        for (int i = lane; i < 456; i += 32) {
            float sc = gam[i] * rsqrtf(var[i] + 1e-3f);
            acc += (bet[i] - mu[i] * sc) * ffnW1[i * 80 + j];
        }
        #pragma unroll
        for (int o = 16; o > 0; o >>= 1) acc += __shfl_xor_sync(0xffffffffu, acc, o);
        if (lane == 0) g_b1f[j] = ffnb1[j] + acc;
    } else if (idx < 54400) {
        int t = idx - 39040;            // 15360 bf16 pairs: n = t/192, k2 = (t%192)*2
        int k2 = (t % 192) * 2;
        int n = t / 192;
        float v[2];
        #pragma unroll
        for (int u = 0; u < 2; u++) {
            int k = k2 + u;
            float w;
            if (k < 128)       w = attW1[(128 + k) * 80 + n] - attW1[(256 + k) * 80 + n];
            else if (k < 256)  w = attW1[(384 + (k - 128)) * 80 + n];
            else { int kk = k - 256; w = attW1[kk * 80 + n] + attW1[(256 + kk) * 80 + n]; }
            v[u] = w;
        }
        ((uint32_t*)g_Wb)[t] = bf2_(v[0], v[1]);
    } else if (idx < 56000) {
        int t = idx - 54400;            // 1600 pairs: n = t/40, k2 = (t%40)*2
        int n = t / 40, k2 = (t % 40) * 2;
        ((uint32_t*)g_W2b)[t] = bf2_(attW2[k2 * 40 + n], attW2[(k2 + 1) * 40 + n]);
    }
}

// ---------------- att: warp-MMA attention MLP, 128 rows per CTA ----------------
// smem bytes: W1 [80][784], A [128][800], W2 [40][176], params
#define AT_W1   0
#define AT_A    62720
#define AT_W2   165120
#define AT_B1   172160
#define AT_B2   172480
#define AT_WF   172640
#define AT_BF   172800
#define AT_SMEM 172816

__global__ void __launch_bounds__(256, 1) din_att(
    const int* __restrict__ seq, const int* __restrict__ item,
    const float* __restrict__ emb_seq,
    const float* __restrict__ att_b1, const float* __restrict__ att_b2,
    const float* __restrict__ attWf, const float* __restrict__ att_bf)
{
    extern __shared__ char smem[];
    float* smf = (float*)smem;
    const uint32_t sb = smem_u32_(smem);
    const int tid = threadIdx.x;
    const int m0 = blockIdx.x * 128;

    // ---- stage weights ----
    const float4* wb4 = (const float4*)g_Wb;       // 3840 f4, rows of 48
    for (int i = tid; i < 3840; i += 256) {
        int rr = i / 48, cc = i - rr * 48;
        *(float4*)(smem + AT_W1 + rr * 784 + cc * 16) = wb4[i];
    }
    const float4* w24 = (const float4*)g_W2b;      // 400 f4, rows of 10
    for (int i = tid; i < 400; i += 256) {
        int rr = i / 10, cc = i - rr * 10;
        *(float4*)(smem + AT_W2 + rr * 176 + cc * 16) = w24[i];
    }
    if (tid < 80) smf[AT_B1 / 4 + tid] = att_b1[tid];
    else if (tid < 120) smf[AT_B2 / 4 + tid - 80] = att_b2[tid - 80];
    else if (tid < 160) smf[AT_WF / 4 + tid - 120] = attWf[tid - 120];
    else if (tid == 160) smf[AT_BF / 4] = att_bf[0];

    // ---- gather + convert A tile: row r = tid>>1, table half h = tid&1 ----
    {
        const int r = tid >> 1, h = tid & 1;
        const int m = m0 + r;
        const int b = m / 40, l = m - b * 40;
        const int sid = seq[(b * 40 + l) * 2 + h];
        const int qid = item[b * 2 + h];
        const float4* sp = (const float4*)(emb_seq + ((size_t)h * VV + sid) * 64);
        const float4* qp = (const float4*)(emb_seq + ((size_t)h * VV + qid) * 64);
        #pragma unroll
        for (int c = 0; c < 16; c++) {
            float4 s = sp[c];
            float4 q = qp[c];
            int k0 = h * 64 + c * 4;
            asm volatile("st.shared.v2.u32 [%0], {%1, %2};"
                         :: "r"(sb + AT_A + r * 800 + k0 * 2),
                            "r"(bf2_(s.x, s.y)), "r"(bf2_(s.z, s.w)));
            asm volatile("st.shared.v2.u32 [%0], {%1, %2};"
                         :: "r"(sb + AT_A + r * 800 + (128 + k0) * 2),
                            "r"(bf2_(s.x * q.x, s.y * q.y)), "r"(bf2_(s.z * q.z, s.w * q.w)));
            asm volatile("st.shared.v2.u32 [%0], {%1, %2};"
                         :: "r"(sb + AT_A + r * 800 + (256 + k0) * 2),
                            "r"(bf2_(q.x, q.y)), "r"(bf2_(q.z, q.w)));
        }
    }
    __syncthreads();

    // ---- MMA1: warp w rows [16w,16w+16) : [16,384]@[384,80] ----
    const int w = tid >> 5, lane = tid & 31;
    float c1[10][4];
    #pragma unroll
    for (int nt = 0; nt < 10; nt++)
        #pragma unroll
        for (int u = 0; u < 4; u++) c1[nt][u] = 0.f;

    const uint32_t aAddrBase = sb + AT_A + (w * 16 + (lane & 15)) * 800 + (lane >> 4) * 16;
    const uint32_t bAddrBase = sb + AT_W1 + (lane & 7) * 784 + ((lane >> 3) & 1) * 16;
    #pragma unroll 8
    for (int kt = 0; kt < 24; kt++) {
        uint32_t a0, a1, a2, a3;
        LDSM4(a0, a1, a2, a3, aAddrBase + kt * 32);
        #pragma unroll
        for (int nt = 0; nt < 10; nt++) {
            uint32_t b0, b1;
            LDSM2(b0, b1, bAddrBase + nt * 8 * 784 + kt * 32);
            MMA16816(c1[nt], a0, a1, a2, a3, b0, b1);
        }
    }

    // ---- epilogue 1 (in registers): sigmoid(c1+b1) -> bf16 A2 fragments ----
    uint32_t p[10][2];
    {
        const int jq = (lane & 3) * 2;
        #pragma unroll
        for (int nt = 0; nt < 10; nt++) {
            int ja = nt * 8 + jq;
            float bj0 = smf[AT_B1 / 4 + ja], bj1 = smf[AT_B1 / 4 + ja + 1];
            p[nt][0] = bf2_(sigmoidf_(c1[nt][0] + bj0), sigmoidf_(c1[nt][1] + bj1));
            p[nt][1] = bf2_(sigmoidf_(c1[nt][2] + bj0), sigmoidf_(c1[nt][3] + bj1));
        }
    }

    // ---- MMA2: [16,80]@[80,40] ----
    float c2[5][4];
    #pragma unroll
    for (int nt = 0; nt < 5; nt++)
        #pragma unroll
        for (int u = 0; u < 4; u++) c2[nt][u] = 0.f;
    const uint32_t b2AddrBase = sb + AT_W2 + (lane & 7) * 176 + ((lane >> 3) & 1) * 16;
    #pragma unroll
    for (int kt = 0; kt < 5; kt++) {
        uint32_t a0 = p[2 * kt][0], a1 = p[2 * kt][1];
        uint32_t a2 = p[2 * kt + 1][0], a3 = p[2 * kt + 1][1];
        #pragma unroll
        for (int nt = 0; nt < 5; nt++) {
            uint32_t b0, b1;
            LDSM2(b0, b1, b2AddrBase + nt * 8 * 176 + kt * 32);
            MMA16816(c2[nt], a0, a1, a2, a3, b0, b1);
        }
    }

    // ---- epilogue 2: logits via quad reduce ----
    {
        float p0 = 0.f, p1 = 0.f;
        const int jq = (lane & 3) * 2;
        #pragma unroll
        for (int nt = 0; nt < 5; nt++) {
            int ja = nt * 8 + jq;
            float bj0 = smf[AT_B2 / 4 + ja], bj1 = smf[AT_B2 / 4 + ja + 1];
            float wf0 = smf[AT_WF / 4 + ja], wf1 = smf[AT_WF / 4 + ja + 1];
            p0 = fmaf(sigmoidf_(c2[nt][0] + bj0), wf0, p0);
            p0 = fmaf(sigmoidf_(c2[nt][1] + bj1), wf1, p0);
            p1 = fmaf(sigmoidf_(c2[nt][2] + bj0), wf0, p1);
            p1 = fmaf(sigmoidf_(c2[nt][3] + bj1), wf1, p1);
        }
        p0 += __shfl_xor_sync(0xffffffffu, p0, 1);
        p0 += __shfl_xor_sync(0xffffffffu, p0, 2);
        p1 += __shfl_xor_sync(0xffffffffu, p1, 1);
        p1 += __shfl_xor_sync(0xffffffffu, p1, 2);
        if ((lane & 3) == 0) {
            float bf = smf[AT_BF / 4];
            int g = lane >> 2;
            int m = m0 + w * 16 + g;
            g_LOG[m] = p0 + bf;
            g_LOG[m + 8] = p1 + bf;
        }
    }
}

// ---------------- pool: softmax + attention pooling + assemble x[456] ----------------
__global__ void __launch_bounds__(128) din_pool(
    const float* __restrict__ dense, const int* __restrict__ sparse,
    const int* __restrict__ seq, const int* __restrict__ item,
    const float* __restrict__ emb_sp, const float* __restrict__ emb_seq)
{
    __shared__ float S[40 * 132];
    __shared__ float LG[40], AT[40], RED[2];
    const int b = blockIdx.x;
    const int tid = threadIdx.x;

    for (int f = tid; f < 1280; f += 128) {
        int l = f >> 5, rr = f & 31, h = rr >> 4, o = rr & 15;
        int row = seq[(b * 40 + l) * 2 + h];
        float4 v = *(const float4*)(emb_seq + ((size_t)h * VV + row) * 64 + o * 4);
        *(float4*)(S + l * 132 + h * 64 + o * 4) = v;
    }
    if (tid < 40) {
        float lg = g_LOG[(size_t)b * 40 + tid];
        int id0 = seq[(b * 40 + tid) * 2];
        LG[tid] = (id0 != 0) ? lg : -4294967295.0f;
    }
    __syncthreads();
    if (tid < 32) {
        float v = LG[tid];
        if (tid < 8) v = fmaxf(v, LG[32 + tid]);
        #pragma unroll
        for (int o = 16; o > 0; o >>= 1) v = fmaxf(v, __shfl_xor_sync(0xffffffffu, v, o));
        if (tid == 0) RED[0] = v;
    }
    __syncthreads();
    if (tid < 40) AT[tid] = __expf(LG[tid] - RED[0]);
    __syncthreads();
    if (tid < 32) {
        float v = AT[tid];
        if (tid < 8) v += AT[32 + tid];
        #pragma unroll
        for (int o = 16; o > 0; o >>= 1) v += __shfl_xor_sync(0xffffffffu, v, o);
        if (tid == 0) RED[1] = 1.f / v;
    }
    float* xb = g_X + (size_t)b * ALLD;
    {
        int h = tid >> 6, e = tid & 63;
        int row = item[b * 2 + h];
        xb[128 + tid] = emb_seq[((size_t)h * VV + row) * 64 + e];
    }
    if (tid < 8) xb[256 + tid] = dense[b * 8 + tid];
    for (int i = tid; i < 192; i += 128) {
        int f = i >> 6, e = i & 63;
        xb[264 + i] = emb_sp[((size_t)f * VV + sparse[b * 3 + f]) * 64 + e];
    }
    __syncthreads();
    float inv = RED[1];
    float u = 0.f;
    #pragma unroll 8
    for (int l = 0; l < 40; l++) u = fmaf(AT[l], S[l * 132 + tid], u);
    xb[tid] = u * inv;
}

// ---------------- FFN: 64 batch rows per CTA ----------------
#define FS_XS   0
#define FS_WCT  29440
#define FS_F1   41600
#define FS_W2   46784
#define FS_F2   50304
#define FS_B1F  52928
#define FS_A1P  53008
#define FS_B2P  53088
#define FS_A2P  53128
#define FS_WO   53168
#define SM_FFN_FLOATS 53208

__global__ void __launch_bounds__(256, 1) din_ffn(
    const float* __restrict__ a1, const float* __restrict__ W2,
    const float* __restrict__ b2, const float* __restrict__ a2,
    const float* __restrict__ outW, const float* __restrict__ outB,
    float* __restrict__ out)
{
    extern __shared__ float sm[];
    const int tid = threadIdx.x;
    const int b0 = blockIdx.x * 64;

    const float4* X4 = (const float4*)g_X;
    for (int i = tid; i < 64 * 114; i += 256) {
        int r = i / 114, c = i % 114;
        *(float4*)(sm + FS_XS + r * 460 + c * 4) = X4[(size_t)(b0 + r) * 114 + c];
    }
    for (int i = tid; i < 800; i += 256) {
        int r = i / 10, c = (i % 10) * 4;
        *(float4*)(sm + FS_W2 + r * 44 + c) = ((const float4*)W2)[i];
    }
    if (tid < 80)  sm[FS_B1F + tid] = g_b1f[tid];
    if (tid >= 80 && tid < 160)  sm[FS_A1P + tid - 80] = a1[tid - 80];
    if (tid >= 160 && tid < 200) sm[FS_B2P + tid - 160] = b2[tid - 160];
    if (tid >= 200 && tid < 240) sm[FS_A2P + tid - 200] = a2[tid - 200];
    if (tid < 40) sm[FS_WO + tid] = outW[tid];

    int jg = tid % 10, bg = tid / 10;
    int j0 = jg * 8, bb = bg * 4;
    ull acc[4][4];
    #pragma unroll
    for (int bi = 0; bi < 4; bi++)
        #pragma unroll
        for (int jp = 0; jp < 4; jp++) acc[bi][jp] = 0ull;

    const float4* W1f4 = (const float4*)g_W1f;
    for (int cch = 0; cch < 3; cch++) {
        __syncthreads();
        for (int i = tid; i < 3040; i += 256)
            *(float4*)(sm + FS_WCT + i * 4) = W1f4[cch * 3040 + i];
        __syncthreads();
        if (tid < 160) {
            #pragma unroll 2
            for (int kk = 0; kk < 152; kk++) {
                int k = cch * 152 + kk;
                ull w[4];
                #pragma unroll
                for (int jp = 0; jp < 4; jp++)
                    w[jp] = *(const ull*)(sm + FS_WCT + kk * 80 + j0 + jp * 2);
                #pragma unroll
                for (int bi = 0; bi < 4; bi++) {
                    float xv = sm[FS_XS + (bb + bi) * 460 + k];
                    ull xs = pack2_(xv, xv);
                    #pragma unroll
                    for (int jp = 0; jp < 4; jp++) FFMA2(acc[bi][jp], xs, w[jp], acc[bi][jp]);
                }
            }
        }
    }
    if (tid < 160) {
        #pragma unroll
        for (int bi = 0; bi < 4; bi++)
            #pragma unroll
            for (int jp = 0; jp < 4; jp++) {
                float x, y; unpack2_(acc[bi][jp], x, y);
                int j = j0 + jp * 2;
                float h0 = x + sm[FS_B1F + j];
                float h1 = y + sm[FS_B1F + j + 1];
                h0 = h0 > 0.f ? h0 : sm[FS_A1P + j] * h0;
                h1 = h1 > 0.f ? h1 : sm[FS_A1P + j + 1] * h1;
                sm[FS_F1 + (bb + bi) * 81 + j] = h0;
                sm[FS_F1 + (bb + bi) * 81 + j + 1] = h1;
            }
    }
    __syncthreads();

    if (tid < 160) {
        int bg2 = tid / 10, jg2 = tid % 10;
        int bb2 = bg2 * 4, j02 = jg2 * 4;
        float acc2[4][4];
        #pragma unroll
        for (int a = 0; a < 4; a++)
            #pragma unroll
            for (int c = 0; c < 4; c++) acc2[a][c] = 0.f;
        #pragma unroll 4
        for (int k = 0; k < 80; k++) {
            float x0 = sm[FS_F1 + (bb2 + 0) * 81 + k];
            float x1 = sm[FS_F1 + (bb2 + 1) * 81 + k];
            float x2 = sm[FS_F1 + (bb2 + 2) * 81 + k];
            float x3 = sm[FS_F1 + (bb2 + 3) * 81 + k];
            float w0 = sm[FS_W2 + k * 44 + j02 + 0];
            float w1 = sm[FS_W2 + k * 44 + j02 + 1];
            float w2 = sm[FS_W2 + k * 44 + j02 + 2];
            float w3 = sm[FS_W2 + k * 44 + j02 + 3];
            acc2[0][0] = fmaf(x0, w0, acc2[0][0]); acc2[0][1] = fmaf(x0, w1, acc2[0][1]);
            acc2[0][2] = fmaf(x0, w2, acc2[0][2]); acc2[0][3] = fmaf(x0, w3, acc2[0][3]);
            acc2[1][0] = fmaf(x1, w0, acc2[1][0]); acc2[1][1] = fmaf(x1, w1, acc2[1][1]);
            acc2[1][2] = fmaf(x1, w2, acc2[1][2]); acc2[1][3] = fmaf(x1, w3, acc2[1][3]);
            acc2[2][0] = fmaf(x2, w0, acc2[2][0]); acc2[2][1] = fmaf(x2, w1, acc2[2][1]);
            acc2[2][2] = fmaf(x2, w2, acc2[2][2]); acc2[2][3] = fmaf(x2, w3, acc2[2][3]);
            acc2[3][0] = fmaf(x3, w0, acc2[3][0]); acc2[3][1] = fmaf(x3, w1, acc2[3][1]);
            acc2[3][2] = fmaf(x3, w2, acc2[3][2]); acc2[3][3] = fmaf(x3, w3, acc2[3][3]);
        }
        #pragma unroll
        for (int bi = 0; bi < 4; bi++)
            #pragma unroll
            for (int jj = 0; jj < 4; jj++) {
                int j = j02 + jj;
                float h = acc2[bi][jj] + sm[FS_B2P + j];
                sm[FS_F2 + (bb2 + bi) * 41 + j] = h > 0.f ? h : sm[FS_A2P + j] * h;
            }
    }
    __syncthreads();

    if (tid < 64) {
        float acc3 = outB[0];
        #pragma unroll 8
        for (int k = 0; k < 40; k++) acc3 = fmaf(sm[FS_F2 + tid * 41 + k], sm[FS_WO + k], acc3);
        out[b0 + tid] = sigmoidf_(acc3);
    }
}

// ---------------- launch ----------------
extern "C" void kernel_launch(void* const* d_in, const int* in_sizes, int n_in,
                              void* d_out, int out_size)
{
    const float* dense = (const float*)d_in[0];
    const int*   sparse = (const int*)d_in[1];
    const int*   seq = (const int*)d_in[2];
    const int*   item = (const int*)d_in[3];
    const float* emb_sp = (const float*)d_in[4];
    const float* embsq = (const float*)d_in[5];
    const float* attW1 = (const float*)d_in[6];
    const float* attb1 = (const float*)d_in[7];
    const float* attW2 = (const float*)d_in[8];
    const float* attb2 = (const float*)d_in[9];
    const float* attWf = (const float*)d_in[10];
    const float* attbf = (const float*)d_in[11];
    const float* gam = (const float*)d_in[12];
    const float* bet = (const float*)d_in[13];
    const float* mu = (const float*)d_in[14];
    const float* var = (const float*)d_in[15];
    const float* fW1 = (const float*)d_in[16];
    const float* fb1 = (const float*)d_in[17];
    const float* fa1 = (const float*)d_in[18];
    const float* fW2 = (const float*)d_in[19];
    const float* fb2 = (const float*)d_in[20];
    const float* fa2 = (const float*)d_in[21];
    const float* oW = (const float*)d_in[22];
    const float* oB = (const float*)d_in[23];
    float* out = (float*)d_out;

    cudaFuncSetAttribute(din_att, cudaFuncAttributeMaxDynamicSharedMemorySize, AT_SMEM);
    cudaFuncSetAttribute(din_ffn, cudaFuncAttributeMaxDynamicSharedMemorySize, SM_FFN_FLOATS * 4);

    din_prep<<<219, 256>>>(attW1, attW2, fW1, fb1, gam, bet, mu, var);
    din_att<<<(BB * LL) / 128, 256, AT_SMEM>>>(seq, item, embsq, attb1, attb2, attWf, attbf);
    din_pool<<<BB, 128>>>(dense, sparse, seq, item, emb_sp, embsq);
    din_ffn<<<BB / 64, 256, SM_FFN_FLOATS * 4>>>(fa1, fW2, fb2, fa2, oW, oB, out);
}